// round 15
// baseline (speedup 1.0000x reference)
#include <cuda_runtime.h>
#include <cuda_fp16.h>
#include <cstdint>

#define NNODES 1000000
#define NGRAPHS 16384
#define NF 128          // node features (= K of GEMM)
#define GF 64           // global features
#define HID 64          // hidden (= N of GEMM)

// ---------------------------------------------------------------------------
// Scratch (device globals — no allocations allowed)
// ---------------------------------------------------------------------------
__device__ float g_U[NGRAPHS * HID];   // u @ W1u + b1
__device__ float g_E[NGRAPHS];         // sum exp(s) per graph (unnormalized)
__device__ unsigned int g_cnt[2];      // grid-barrier arrive counters
__device__ unsigned int g_ep[2];       // grid-barrier epochs (monotonic)

// ---------------------------------------------------------------------------
// fp16 helpers
// ---------------------------------------------------------------------------
__device__ __forceinline__ uint32_t h2pack(float f0, float f1) {
    __half2 h = __floats2half2_rn(f0, f1);     // low = f0 (lower-k element)
    return *reinterpret_cast<uint32_t*>(&h);
}

__device__ __forceinline__ void mma16816h(float c[4], const uint32_t a[4],
                                          uint32_t b0, uint32_t b1) {
    asm volatile(
        "mma.sync.aligned.m16n8k16.row.col.f32.f16.f16.f32 "
        "{%0,%1,%2,%3}, {%4,%5,%6,%7}, {%8,%9}, {%0,%1,%2,%3};"
        : "+f"(c[0]), "+f"(c[1]), "+f"(c[2]), "+f"(c[3])
        : "r"(a[0]), "r"(a[1]), "r"(a[2]), "r"(a[3]), "r"(b0), "r"(b1));
}

// ---------------------------------------------------------------------------
// Grid barrier (epoch-based, launch-safe: epoch is monotonic across replays).
// Grid is exactly co-resident (592 = 148 SMs x 4 CTAs via launch bounds).
// ---------------------------------------------------------------------------
__device__ __forceinline__ void grid_barrier(int idx, unsigned int nblk) {
    __syncthreads();
    if (threadIdx.x == 0) {
        volatile unsigned int* ep = &g_ep[idx];
        unsigned int my = *ep;
        __threadfence();
        unsigned int old = atomicAdd(&g_cnt[idx], 1u);
        if (old == nblk - 1u) {
            atomicExch(&g_cnt[idx], 0u);
            __threadfence();
            atomicAdd(&g_ep[idx], 1u);
        } else {
            while (*ep == my) __nanosleep(64);
            __threadfence();
        }
    }
    __syncthreads();
}

// ---------------------------------------------------------------------------
// ONE persistent kernel: prologue (U proj + zero) -> barrier -> fused
// MLP+pool tile loop (R14 winner, untouched) -> barrier -> normalize.
// ---------------------------------------------------------------------------
struct SmemMMA {
    union {
        float w1u[GF * HID];    // prologue: W1u staging (16KB)
        uint2 B[64 * 32];       // mainloop: [kk*8+nt][lane] fragments (16KB)
    } ub;
    float w2[HID];
    float b2v;
};

__global__ __launch_bounds__(128, 4)
void k_all(const float* __restrict__ x, const float* __restrict__ u,
           const int* __restrict__ batch, const float* __restrict__ W1,
           const float* __restrict__ b1, const float* __restrict__ W2,
           const float* __restrict__ b2, float* __restrict__ pooled,
           float* __restrict__ attn, int n, int ntiles) {
    __shared__ SmemMMA sm;
    const int tid  = threadIdx.x;
    const int wid  = tid >> 5;
    const int lane = tid & 31;
    const int g8   = lane >> 2;          // groupID 0..7
    const int quad = lane & 3;           // 0..3
    const unsigned int nblk = gridDim.x;

    // ===== PROLOGUE: U = u @ W1u + b1 ; zero pooled/g_E ====================
    for (int i = tid; i < GF * HID; i += 128)
        sm.ub.w1u[i] = __ldg(W1 + NF * HID + i);     // w1u[k*64 + j]
    __syncthreads();

    {   // per-warp U rows: warp owns graph g, lane covers j and j+32
        float b1a = __ldg(b1 + lane);
        float b1b = __ldg(b1 + lane + 32);
        for (int g = blockIdx.x * 4 + wid; g < NGRAPHS; g += nblk * 4) {
            float u0 = __ldg(u + g * GF + lane);
            float u1 = __ldg(u + g * GF + lane + 32);
            float acc0 = b1a, acc1 = b1b;
#pragma unroll
            for (int k = 0; k < 32; k++) {
                float uk = __shfl_sync(0xFFFFFFFF, u0, k);
                acc0 = fmaf(uk, sm.ub.w1u[k * HID + lane], acc0);
                acc1 = fmaf(uk, sm.ub.w1u[k * HID + lane + 32], acc1);
            }
#pragma unroll
            for (int k = 0; k < 32; k++) {
                float uk = __shfl_sync(0xFFFFFFFF, u1, k);
                acc0 = fmaf(uk, sm.ub.w1u[(k + 32) * HID + lane], acc0);
                acc1 = fmaf(uk, sm.ub.w1u[(k + 32) * HID + lane + 32], acc1);
            }
            g_U[g * HID + lane]      = acc0;
            g_U[g * HID + lane + 32] = acc1;
        }
    }
    {   // zero pooled + g_E (grid-stride)
        float4* p4 = (float4*)pooled;
        const int np4 = NGRAPHS * NF / 4;
        for (int i = blockIdx.x * 128 + tid; i < np4; i += nblk * 128)
            p4[i] = make_float4(0.f, 0.f, 0.f, 0.f);
        for (int i = blockIdx.x * 128 + tid; i < NGRAPHS; i += nblk * 128)
            g_E[i] = 0.f;
    }
    __syncthreads();   // w1u no longer needed

    // stage B fragments (W1x^T fp16, sigma-permuted) over the union buffer
    for (int e = wid; e < 64; e += 4) {
        int nt = e & 7;
        int kk = e >> 3;
        int nn = nt * 8 + g8;
        int k0 = kk * 16 + quad * 4;
        float w0 = __ldg(W1 + (k0 + 0) * HID + nn);
        float w1 = __ldg(W1 + (k0 + 1) * HID + nn);
        float w2v = __ldg(W1 + (k0 + 2) * HID + nn);
        float w3 = __ldg(W1 + (k0 + 3) * HID + nn);
        sm.ub.B[e * 32 + lane] = make_uint2(h2pack(w0, w1), h2pack(w2v, w3));
    }
    if (tid < HID) sm.w2[tid] = __ldg(W2 + tid);
    if (tid == 0) sm.b2v = __ldg(b2);

    grid_barrier(0, nblk);   // U + zeros visible everywhere; B staged locally

    // ===== MAIN TILE LOOP (R14 winner, unchanged) ==========================
    for (int t = blockIdx.x; t < ntiles; t += nblk) {
        const int rowbase = t * 128 + wid * 32;

        int r0 = rowbase + g8;
        int cc0 = min(r0,      n - 1);
        int cc1 = min(r0 + 8,  n - 1);
        int cc2 = min(r0 + 16, n - 1);
        int cc3 = min(r0 + 24, n - 1);
        const float4* xp0 = (const float4*)(x + (size_t)cc0 * NF);
        const float4* xp1 = (const float4*)(x + (size_t)cc1 * NF);
        const float4* xp2 = (const float4*)(x + (size_t)cc2 * NF);
        const float4* xp3 = (const float4*)(x + (size_t)cc3 * NF);

        int gj[4];
        gj[0] = __ldg(batch + cc0);
        gj[1] = __ldg(batch + cc1);
        gj[2] = __ldg(batch + cc2);
        gj[3] = __ldg(batch + cc3);

        float c[2][8][4];
#pragma unroll
        for (int mt = 0; mt < 2; mt++)
#pragma unroll
            for (int nt = 0; nt < 8; nt++)
#pragma unroll
                for (int i = 0; i < 4; i++) c[mt][nt][i] = 0.f;

#pragma unroll 4
        for (int kk = 0; kk < 8; kk++) {
            float4 va = __ldg(xp0 + kk * 4 + quad);
            float4 vb = __ldg(xp1 + kk * 4 + quad);
            float4 vc = __ldg(xp2 + kk * 4 + quad);
            float4 vd = __ldg(xp3 + kk * 4 + quad);

            uint32_t a0[4], a1[4];
            a0[0] = h2pack(va.x, va.y);
            a0[1] = h2pack(vb.x, vb.y);
            a0[2] = h2pack(va.z, va.w);
            a0[3] = h2pack(vb.z, vb.w);
            a1[0] = h2pack(vc.x, vc.y);
            a1[1] = h2pack(vd.x, vd.y);
            a1[2] = h2pack(vc.z, vc.w);
            a1[3] = h2pack(vd.z, vd.w);

#pragma unroll
            for (int nt = 0; nt < 8; nt++) {
                uint2 b = sm.ub.B[(kk * 8 + nt) * 32 + lane];
                mma16816h(c[0][nt], a0, b.x, b.y);
                mma16816h(c[1][nt], a1, b.x, b.y);
            }
        }

        // epilogue: s = W2 . relu(c + U) + b2; exp(s) -> attn (unnormalized)
        float ej[4];
#pragma unroll
        for (int mt = 0; mt < 2; mt++) {
            const float* Ua = g_U + gj[2 * mt] * HID;
            const float* Ub = g_U + gj[2 * mt + 1] * HID;
            float sa = 0.f, sb = 0.f;
#pragma unroll
            for (int nt = 0; nt < 8; nt++) {
                int n0 = nt * 8 + quad * 2;
                float2 ua = *(const float2*)(Ua + n0);
                float2 ub = *(const float2*)(Ub + n0);
                float w0 = sm.w2[n0], w1 = sm.w2[n0 + 1];
                sa = fmaf(w0, fmaxf(c[mt][nt][0] + ua.x, 0.f), sa);
                sa = fmaf(w1, fmaxf(c[mt][nt][1] + ua.y, 0.f), sa);
                sb = fmaf(w0, fmaxf(c[mt][nt][2] + ub.x, 0.f), sb);
                sb = fmaf(w1, fmaxf(c[mt][nt][3] + ub.y, 0.f), sb);
            }
            sa += __shfl_xor_sync(0xFFFFFFFF, sa, 1);
            sa += __shfl_xor_sync(0xFFFFFFFF, sa, 2);
            sb += __shfl_xor_sync(0xFFFFFFFF, sb, 1);
            sb += __shfl_xor_sync(0xFFFFFFFF, sb, 2);
            float eva = __expf(sa + sm.b2v);
            float evb = __expf(sb + sm.b2v);
            int ra = rowbase + mt * 16 + g8, rb = ra + 8;
            ej[2 * mt]     = (ra < n) ? eva : 0.f;
            ej[2 * mt + 1] = (rb < n) ? evb : 0.f;
            if (quad == 0) {
                if (ra < n) attn[ra] = eva;
                if (rb < n) attn[rb] = evb;
            }
        }

        // prefetch next tile's x rows into L1 (overlap with phase 2)
        {
            int t2 = t + nblk;
            if (t2 < ntiles) {
                int rowbase2 = t2 * 128 + wid * 32;
#pragma unroll
                for (int pf = 0; pf < 4; pf++) {
                    int row = min(rowbase2 + pf * 8 + (lane >> 2), n - 1);
                    const float* p = x + (size_t)row * NF + (lane & 3) * 32;
                    asm volatile("prefetch.global.L1 [%0];" :: "l"(p));
                }
            }
        }

        // phase 2 (warp-local): pool this warp's 32 rows
        {
            float4 acc = make_float4(0.f, 0.f, 0.f, 0.f);
            float acce = 0.f;
            int curg = __shfl_sync(0xFFFFFFFF, gj[0], 0);
#pragma unroll
            for (int r = 0; r < 32; r++) {
                int j   = r >> 3;
                int src = (r & 7) * 4;
                float e = __shfl_sync(0xFFFFFFFF, ej[j], src);
                int   g = __shfl_sync(0xFFFFFFFF, gj[j], src);
                if (g != curg) {
                    float* dst = pooled + (size_t)curg * NF + lane * 4;
                    atomicAdd(dst + 0, acc.x);
                    atomicAdd(dst + 1, acc.y);
                    atomicAdd(dst + 2, acc.z);
                    atomicAdd(dst + 3, acc.w);
                    if (lane == 0) atomicAdd(&g_E[curg], acce);
                    acc = make_float4(0.f, 0.f, 0.f, 0.f);
                    acce = 0.f;
                    curg = g;
                }
                int rr = min(rowbase + r, n - 1);
                float4 xv = __ldg((const float4*)(x + (size_t)rr * NF) + lane);
                acc.x = fmaf(xv.x, e, acc.x);
                acc.y = fmaf(xv.y, e, acc.y);
                acc.z = fmaf(xv.z, e, acc.z);
                acc.w = fmaf(xv.w, e, acc.w);
                acce += e;
            }
            float* dst = pooled + (size_t)curg * NF + lane * 4;
            atomicAdd(dst + 0, acc.x);
            atomicAdd(dst + 1, acc.y);
            atomicAdd(dst + 2, acc.z);
            atomicAdd(dst + 3, acc.w);
            if (lane == 0) atomicAdd(&g_E[curg], acce);
        }
    }

    grid_barrier(1, nblk);   // all atomics + attn stores done

    // ===== EPILOGUE: normalize pooled and attn (L2 reads via ldcg) =========
    {
        float4* p4 = (float4*)pooled;
        const int np4 = NGRAPHS * NF / 4;
        for (int i = blockIdx.x * 128 + tid; i < np4; i += nblk * 128) {
            float E = __ldcg(&g_E[i >> 5]);
            float inv = (E > 0.f) ? __fdividef(1.f, E) : 0.f;
            float4 v = __ldcg(p4 + i);
            v.x *= inv; v.y *= inv; v.z *= inv; v.w *= inv;
            p4[i] = v;
        }
        const int na4 = n >> 2;
        for (int i = blockIdx.x * 128 + tid; i < na4; i += nblk * 128) {
            float4 a = __ldcg((const float4*)(attn) + i);
            int4   b = *(const int4*)(batch + i * 4);
            a.x *= __fdividef(1.f, __ldcg(&g_E[b.x]));
            a.y *= __fdividef(1.f, __ldcg(&g_E[b.y]));
            a.z *= __fdividef(1.f, __ldcg(&g_E[b.z]));
            a.w *= __fdividef(1.f, __ldcg(&g_E[b.w]));
            ((float4*)attn)[i] = a;
        }
        for (int j = na4 * 4 + blockIdx.x * 128 + tid; j < n; j += nblk * 128)
            attn[j] = __ldcg(attn + j) * __fdividef(1.f, __ldcg(&g_E[__ldg(batch + j)]));
    }
}

// ---------------------------------------------------------------------------
extern "C" void kernel_launch(void* const* d_in, const int* in_sizes, int n_in,
                              void* d_out, int out_size) {
    const float* x     = (const float*)d_in[0];
    const float* u     = (const float*)d_in[1];
    const int*   batch = (const int*)  d_in[2];
    const float* W1    = (const float*)d_in[3];
    const float* b1    = (const float*)d_in[4];
    const float* W2    = (const float*)d_in[5];
    const float* b2    = (const float*)d_in[6];

    float* pooled = (float*)d_out;                     // [16384, 128]
    float* attn   = (float*)d_out + NGRAPHS * NF;      // [1e6]

    int n = in_sizes[2];
    int ntiles = (n + 127) / 128;

    k_all<<<592, 128>>>(x, u, batch, W1, b1, W2, b2, pooled, attn, n, ntiles);
}

// round 16
// speedup vs baseline: 1.0937x; 1.0937x over previous
#include <cuda_runtime.h>
#include <cuda_fp16.h>
#include <cstdint>

#define NNODES 1000000
#define NGRAPHS 16384
#define NF 128          // node features (= K of GEMM)
#define GF 64           // global features
#define HID 64          // hidden (= N of GEMM)

// ---------------------------------------------------------------------------
// Scratch (device globals — no allocations allowed)
// ---------------------------------------------------------------------------
__device__ float g_U[NGRAPHS * HID];   // u @ W1u + b1
__device__ float g_E[NGRAPHS];         // sum exp(s) per graph (unnormalized)

// ---------------------------------------------------------------------------
// k_init: U projection + zero pooled rows + zero g_E (R11/R14 winner).
// ---------------------------------------------------------------------------
__global__ __launch_bounds__(256)
void k_init(const float* __restrict__ u, const float* __restrict__ W1,
            const float* __restrict__ b1, float* __restrict__ pooled) {
    __shared__ float us[4][GF];
    int sub = threadIdx.x >> 6;           // 0..3  graph-group
    int j   = threadIdx.x & 63;           // 0..63
    float wcol[GF];
#pragma unroll
    for (int k = 0; k < GF; k++) wcol[k] = __ldg(W1 + (NF + k) * HID + j);
    float b1j = __ldg(b1 + j);

    for (int g = blockIdx.x * 4 + sub; g < NGRAPHS; g += gridDim.x * 4) {
        us[sub][j] = __ldg(u + g * GF + j);
        ((float2*)(pooled + (size_t)g * NF))[j] = make_float2(0.f, 0.f);
        if (j == 0) g_E[g] = 0.f;
        __syncthreads();
        float acc = b1j;
#pragma unroll
        for (int k = 0; k < GF; k++)
            acc = fmaf(us[sub][k], wcol[k], acc);
        g_U[g * HID + j] = acc;
        __syncthreads();
    }
}

// ---------------------------------------------------------------------------
// fp16 helpers
// ---------------------------------------------------------------------------
__device__ __forceinline__ uint32_t h2pack(float f0, float f1) {
    __half2 h = __floats2half2_rn(f0, f1);     // low = f0 (lower-k element)
    return *reinterpret_cast<uint32_t*>(&h);
}

__device__ __forceinline__ void mma16816h(float c[4], const uint32_t a[4],
                                          uint32_t b0, uint32_t b1) {
    asm volatile(
        "mma.sync.aligned.m16n8k16.row.col.f32.f16.f16.f32 "
        "{%0,%1,%2,%3}, {%4,%5,%6,%7}, {%8,%9}, {%0,%1,%2,%3};"
        : "+f"(c[0]), "+f"(c[1]), "+f"(c[2]), "+f"(c[3])
        : "r"(a[0]), "r"(a[1]), "r"(a[2]), "r"(a[3]), "r"(b0), "r"(b1));
}

// ---------------------------------------------------------------------------
// Fused tensor-core MLP + attention pool — fp16 single-term.
// R16: warp tile 32 -> 16 rows (half the accumulators) to reach 6 CTAs/SM
// (24 warps/SM). Profile showed occ 24%, issue 22%, nothing saturated:
// pure latency-bound -> residency is the lever. Per-row work unchanged.
// ---------------------------------------------------------------------------
struct SmemMMA {
    uint2 B[64 * 32];       // [kk*8+nt][lane] = {b0, b1}  16KB
    float w2[HID];
    float b2v;
};

__global__ __launch_bounds__(128, 6)
void k_mlp_fused(const float* __restrict__ x, const float* __restrict__ W1,
                 const float* __restrict__ W2, const float* __restrict__ b2,
                 const int* __restrict__ batch, float* __restrict__ pooled,
                 float* __restrict__ attn, int n, int ntiles) {
    __shared__ SmemMMA sm;
    const int tid  = threadIdx.x;
    const int wid  = tid >> 5;
    const int lane = tid & 31;
    const int g8   = lane >> 2;          // groupID 0..7
    const int quad = lane & 3;           // 0..3

    // --- stage W1x^T fp16 fragments, sigma-permuted ------------------------
    for (int e = wid; e < 64; e += 4) {
        int nt = e & 7;
        int kk = e >> 3;
        int nn = nt * 8 + g8;
        int k0 = kk * 16 + quad * 4;
        float w0 = W1[(k0 + 0) * HID + nn];
        float w1 = W1[(k0 + 1) * HID + nn];
        float w2v = W1[(k0 + 2) * HID + nn];
        float w3 = W1[(k0 + 3) * HID + nn];
        sm.B[e * 32 + lane] = make_uint2(h2pack(w0, w1), h2pack(w2v, w3));
    }
    if (tid < HID) sm.w2[tid] = W2[tid];
    if (tid == 0) sm.b2v = b2[0];
    __syncthreads();

    for (int t = blockIdx.x; t < ntiles; t += gridDim.x) {
        const int rowbase = t * 64 + wid * 16;     // warp owns 16 rows

        int r0 = rowbase + g8;
        int cc0 = min(r0,     n - 1);
        int cc1 = min(r0 + 8, n - 1);
        const float4* xp0 = (const float4*)(x + (size_t)cc0 * NF);
        const float4* xp1 = (const float4*)(x + (size_t)cc1 * NF);

        int gj[2];
        gj[0] = __ldg(batch + cc0);
        gj[1] = __ldg(batch + cc1);

        float c[8][4];
#pragma unroll
        for (int nt = 0; nt < 8; nt++)
#pragma unroll
            for (int i = 0; i < 4; i++) c[nt][i] = 0.f;

#pragma unroll 4
        for (int kk = 0; kk < 8; kk++) {
            float4 va = __ldg(xp0 + kk * 4 + quad);
            float4 vb = __ldg(xp1 + kk * 4 + quad);

            uint32_t a0[4];
            a0[0] = h2pack(va.x, va.y);
            a0[1] = h2pack(vb.x, vb.y);
            a0[2] = h2pack(va.z, va.w);
            a0[3] = h2pack(vb.z, vb.w);

#pragma unroll
            for (int nt = 0; nt < 8; nt++) {
                uint2 b = sm.B[(kk * 8 + nt) * 32 + lane];
                mma16816h(c[nt], a0, b.x, b.y);
            }
        }

        // --- epilogue: s = W2 . relu(c + U) + b2; exp(s) -> attn -----------
        float ej[2];
        {
            const float* Ua = g_U + gj[0] * HID;
            const float* Ub = g_U + gj[1] * HID;
            float sa = 0.f, sb = 0.f;
#pragma unroll
            for (int nt = 0; nt < 8; nt++) {
                int n0 = nt * 8 + quad * 2;
                float2 ua = *(const float2*)(Ua + n0);
                float2 ub = *(const float2*)(Ub + n0);
                float w0 = sm.w2[n0], w1 = sm.w2[n0 + 1];
                sa = fmaf(w0, fmaxf(c[nt][0] + ua.x, 0.f), sa);
                sa = fmaf(w1, fmaxf(c[nt][1] + ua.y, 0.f), sa);
                sb = fmaf(w0, fmaxf(c[nt][2] + ub.x, 0.f), sb);
                sb = fmaf(w1, fmaxf(c[nt][3] + ub.y, 0.f), sb);
            }
            sa += __shfl_xor_sync(0xFFFFFFFF, sa, 1);
            sa += __shfl_xor_sync(0xFFFFFFFF, sa, 2);
            sb += __shfl_xor_sync(0xFFFFFFFF, sb, 1);
            sb += __shfl_xor_sync(0xFFFFFFFF, sb, 2);
            float eva = __expf(sa + sm.b2v);
            float evb = __expf(sb + sm.b2v);
            int ra = r0, rb = r0 + 8;
            ej[0] = (ra < n) ? eva : 0.f;
            ej[1] = (rb < n) ? evb : 0.f;
            if (quad == 0) {
                if (ra < n) attn[ra] = eva;     // unnormalized; k_final divides
                if (rb < n) attn[rb] = evb;
            }
        }

        // --- prefetch next tile's x rows into L1 (overlap with phase 2) ----
        {
            int t2 = t + gridDim.x;
            if (t2 < ntiles) {
                int rowbase2 = t2 * 64 + wid * 16;
#pragma unroll
                for (int pf = 0; pf < 2; pf++) {
                    int idx = pf * 32 + lane;            // 0..63
                    int row = min(rowbase2 + (idx >> 2), n - 1);
                    const float* p = x + (size_t)row * NF + (idx & 3) * 32;
                    asm volatile("prefetch.global.L1 [%0];" :: "l"(p));
                }
            }
        }

        // --- phase 2 (warp-local): pool this warp's 16 rows ----------------
        {
            float4 acc = make_float4(0.f, 0.f, 0.f, 0.f);
            float acce = 0.f;
            int curg = __shfl_sync(0xFFFFFFFF, gj[0], 0);
#pragma unroll
            for (int r = 0; r < 16; r++) {
                int j   = r >> 3;
                int src = (r & 7) * 4;
                float e = __shfl_sync(0xFFFFFFFF, ej[j], src);
                int   g = __shfl_sync(0xFFFFFFFF, gj[j], src);
                if (g != curg) {
                    float* dst = pooled + (size_t)curg * NF + lane * 4;
                    atomicAdd(dst + 0, acc.x);
                    atomicAdd(dst + 1, acc.y);
                    atomicAdd(dst + 2, acc.z);
                    atomicAdd(dst + 3, acc.w);
                    if (lane == 0) atomicAdd(&g_E[curg], acce);
                    acc = make_float4(0.f, 0.f, 0.f, 0.f);
                    acce = 0.f;
                    curg = g;
                }
                int rr = min(rowbase + r, n - 1);
                float4 xv = __ldg((const float4*)(x + (size_t)rr * NF) + lane);
                acc.x = fmaf(xv.x, e, acc.x);
                acc.y = fmaf(xv.y, e, acc.y);
                acc.z = fmaf(xv.z, e, acc.z);
                acc.w = fmaf(xv.w, e, acc.w);
                acce += e;
            }
            float* dst = pooled + (size_t)curg * NF + lane * 4;
            atomicAdd(dst + 0, acc.x);
            atomicAdd(dst + 1, acc.y);
            atomicAdd(dst + 2, acc.z);
            atomicAdd(dst + 3, acc.w);
            if (lane == 0) atomicAdd(&g_E[curg], acce);
        }
    }
}

// ---------------------------------------------------------------------------
// k_final (vectorized): pooled[i] /= E ; attn[j] /= E[batch[j]]
// ---------------------------------------------------------------------------
__global__ void k_final(const int* __restrict__ batch, float* __restrict__ attn,
                        float* __restrict__ pooled, int n) {
    const int pq = NGRAPHS * NF / 4;          // pooled float4 count
    int i = blockIdx.x * 256 + threadIdx.x;
    if (i < pq) {
        float E = g_E[i >> 5];                // 32 float4 per graph row
        float inv = (E > 0.f) ? __fdividef(1.f, E) : 0.f;
        float4 v = ((float4*)pooled)[i];
        v.x *= inv; v.y *= inv; v.z *= inv; v.w *= inv;
        ((float4*)pooled)[i] = v;
    } else {
        int j4 = (i - pq) * 4;
        if (j4 + 3 < n) {
            float4 a = *(const float4*)(attn + j4);
            int4   b = *(const int4*)(batch + j4);
            a.x *= __fdividef(1.f, g_E[b.x]);
            a.y *= __fdividef(1.f, g_E[b.y]);
            a.z *= __fdividef(1.f, g_E[b.z]);
            a.w *= __fdividef(1.f, g_E[b.w]);
            *(float4*)(attn + j4) = a;
        } else {
            for (int j = j4; j < n; j++)
                attn[j] *= __fdividef(1.f, g_E[__ldg(batch + j)]);
        }
    }
}

// ---------------------------------------------------------------------------
extern "C" void kernel_launch(void* const* d_in, const int* in_sizes, int n_in,
                              void* d_out, int out_size) {
    const float* x     = (const float*)d_in[0];
    const float* u     = (const float*)d_in[1];
    const int*   batch = (const int*)  d_in[2];
    const float* W1    = (const float*)d_in[3];
    const float* b1    = (const float*)d_in[4];
    const float* W2    = (const float*)d_in[5];
    const float* b2    = (const float*)d_in[6];

    float* pooled = (float*)d_out;                     // [16384, 128]
    float* attn   = (float*)d_out + NGRAPHS * NF;      // [1e6]

    int n = in_sizes[2];
    int ntiles = (n + 63) / 64;     // 64-row tiles now
    int nfinal = NGRAPHS * NF / 4 + (n + 3) / 4;

    k_init<<<296, 256>>>(u, W1, b1, pooled);
    k_mlp_fused<<<888, 128>>>(x, W1, W2, b2, batch, pooled, attn, n, ntiles);
    k_final<<<(nfinal + 255) / 256, 256>>>(batch, attn, pooled, n);
}

// round 17
// speedup vs baseline: 1.1597x; 1.0603x over previous
#include <cuda_runtime.h>
#include <cuda_fp16.h>
#include <cstdint>

#define NNODES 1000000
#define NGRAPHS 16384
#define NF 128          // node features (= K of GEMM)
#define GF 64           // global features
#define HID 64          // hidden (= N of GEMM)

// ---------------------------------------------------------------------------
// Scratch (device globals — no allocations allowed)
// ---------------------------------------------------------------------------
__device__ float g_U[NGRAPHS * HID];   // u @ W1u + b1
__device__ float g_E[NGRAPHS];         // sum exp(s) per graph (unnormalized)

// ---------------------------------------------------------------------------
// k_init (warp-per-graph): U = u @ W1u + b1 ; zero pooled row + g_E.
// W1u staged once in smem; u in 2 regs/lane via shfl; no syncs in loop.
// ---------------------------------------------------------------------------
__global__ __launch_bounds__(256)
void k_init(const float* __restrict__ u, const float* __restrict__ W1,
            const float* __restrict__ b1, float* __restrict__ pooled) {
    __shared__ float w1s[GF * HID];     // w1s[k*64+j] = W1[(128+k)*64+j]
    const int tid  = threadIdx.x;
    const int wid  = tid >> 5;
    const int lane = tid & 31;
    for (int i = tid; i < GF * HID; i += 256)
        w1s[i] = __ldg(W1 + NF * HID + i);
    float b1a = __ldg(b1 + lane);
    float b1b = __ldg(b1 + lane + 32);
    __syncthreads();

    for (int g = blockIdx.x * 8 + wid; g < NGRAPHS; g += gridDim.x * 8) {
        float u0 = __ldg(u + g * GF + lane);
        float u1 = __ldg(u + g * GF + lane + 32);
        // zero this graph's pooled row (32 lanes x 16B = 512B) and g_E
        ((float4*)(pooled + (size_t)g * NF))[lane] = make_float4(0.f, 0.f, 0.f, 0.f);
        if (lane == 0) g_E[g] = 0.f;

        float acc0 = b1a, acc1 = b1b;
#pragma unroll
        for (int k = 0; k < 32; k++) {
            float uk = __shfl_sync(0xFFFFFFFF, u0, k);
            acc0 = fmaf(uk, w1s[k * HID + lane], acc0);
            acc1 = fmaf(uk, w1s[k * HID + lane + 32], acc1);
        }
#pragma unroll
        for (int k = 0; k < 32; k++) {
            float uk = __shfl_sync(0xFFFFFFFF, u1, k);
            acc0 = fmaf(uk, w1s[(k + 32) * HID + lane], acc0);
            acc1 = fmaf(uk, w1s[(k + 32) * HID + lane + 32], acc1);
        }
        g_U[g * HID + lane]      = acc0;
        g_U[g * HID + lane + 32] = acc1;
    }
}

// ---------------------------------------------------------------------------
// fp16 helpers + vector reduction
// ---------------------------------------------------------------------------
__device__ __forceinline__ uint32_t h2pack(float f0, float f1) {
    __half2 h = __floats2half2_rn(f0, f1);     // low = f0 (lower-k element)
    return *reinterpret_cast<uint32_t*>(&h);
}

__device__ __forceinline__ void mma16816h(float c[4], const uint32_t a[4],
                                          uint32_t b0, uint32_t b1) {
    asm volatile(
        "mma.sync.aligned.m16n8k16.row.col.f32.f16.f16.f32 "
        "{%0,%1,%2,%3}, {%4,%5,%6,%7}, {%8,%9}, {%0,%1,%2,%3};"
        : "+f"(c[0]), "+f"(c[1]), "+f"(c[2]), "+f"(c[3])
        : "r"(a[0]), "r"(a[1]), "r"(a[2]), "r"(a[3]), "r"(b0), "r"(b1));
}

// vector reduction: one instruction, 4 floats, 16B-aligned dst (sm_90+)
__device__ __forceinline__ void red_add_v4(float* dst, float4 v) {
    asm volatile("red.global.add.v4.f32 [%0], {%1,%2,%3,%4};"
                 :: "l"(dst), "f"(v.x), "f"(v.y), "f"(v.z), "f"(v.w)
                 : "memory");
}

// ---------------------------------------------------------------------------
// Fused tensor-core MLP + attention pool — R14 winner, untouched except the
// pooled flushes now use red.global.add.v4.f32 (4x fewer RED instructions).
// ---------------------------------------------------------------------------
struct SmemMMA {
    uint2 B[64 * 32];       // [kk*8+nt][lane] = {b0, b1}  16KB
    float w2[HID];
    float b2v;
};

__global__ __launch_bounds__(128, 4)
void k_mlp_fused(const float* __restrict__ x, const float* __restrict__ W1,
                 const float* __restrict__ W2, const float* __restrict__ b2,
                 const int* __restrict__ batch, float* __restrict__ pooled,
                 float* __restrict__ attn, int n, int ntiles) {
    __shared__ SmemMMA sm;
    const int tid  = threadIdx.x;
    const int wid  = tid >> 5;
    const int lane = tid & 31;
    const int g8   = lane >> 2;          // groupID 0..7
    const int quad = lane & 3;           // 0..3

    // --- stage W1x^T fp16 fragments, sigma-permuted ------------------------
    for (int e = wid; e < 64; e += 4) {
        int nt = e & 7;
        int kk = e >> 3;
        int nn = nt * 8 + g8;
        int k0 = kk * 16 + quad * 4;
        float w0 = W1[(k0 + 0) * HID + nn];
        float w1 = W1[(k0 + 1) * HID + nn];
        float w2v = W1[(k0 + 2) * HID + nn];
        float w3 = W1[(k0 + 3) * HID + nn];
        sm.B[e * 32 + lane] = make_uint2(h2pack(w0, w1), h2pack(w2v, w3));
    }
    if (tid < HID) sm.w2[tid] = W2[tid];
    if (tid == 0) sm.b2v = b2[0];
    __syncthreads();

    for (int t = blockIdx.x; t < ntiles; t += gridDim.x) {
        const int rowbase = t * 128 + wid * 32;

        int r0 = rowbase + g8;
        int cc0 = min(r0,      n - 1);
        int cc1 = min(r0 + 8,  n - 1);
        int cc2 = min(r0 + 16, n - 1);
        int cc3 = min(r0 + 24, n - 1);
        const float4* xp0 = (const float4*)(x + (size_t)cc0 * NF);
        const float4* xp1 = (const float4*)(x + (size_t)cc1 * NF);
        const float4* xp2 = (const float4*)(x + (size_t)cc2 * NF);
        const float4* xp3 = (const float4*)(x + (size_t)cc3 * NF);

        int gj[4];
        gj[0] = __ldg(batch + cc0);
        gj[1] = __ldg(batch + cc1);
        gj[2] = __ldg(batch + cc2);
        gj[3] = __ldg(batch + cc3);

        float c[2][8][4];
#pragma unroll
        for (int mt = 0; mt < 2; mt++)
#pragma unroll
            for (int nt = 0; nt < 8; nt++)
#pragma unroll
                for (int i = 0; i < 4; i++) c[mt][nt][i] = 0.f;

#pragma unroll 4
        for (int kk = 0; kk < 8; kk++) {
            float4 va = __ldg(xp0 + kk * 4 + quad);
            float4 vb = __ldg(xp1 + kk * 4 + quad);
            float4 vc = __ldg(xp2 + kk * 4 + quad);
            float4 vd = __ldg(xp3 + kk * 4 + quad);

            uint32_t a0[4], a1[4];
            a0[0] = h2pack(va.x, va.y);
            a0[1] = h2pack(vb.x, vb.y);
            a0[2] = h2pack(va.z, va.w);
            a0[3] = h2pack(vb.z, vb.w);
            a1[0] = h2pack(vc.x, vc.y);
            a1[1] = h2pack(vd.x, vd.y);
            a1[2] = h2pack(vc.z, vc.w);
            a1[3] = h2pack(vd.z, vd.w);

#pragma unroll
            for (int nt = 0; nt < 8; nt++) {
                uint2 b = sm.B[(kk * 8 + nt) * 32 + lane];
                mma16816h(c[0][nt], a0, b.x, b.y);
                mma16816h(c[1][nt], a1, b.x, b.y);
            }
        }

        // --- epilogue: s = W2 . relu(c + U) + b2; exp(s) -> attn -----------
        float ej[4];
#pragma unroll
        for (int mt = 0; mt < 2; mt++) {
            const float* Ua = g_U + gj[2 * mt] * HID;
            const float* Ub = g_U + gj[2 * mt + 1] * HID;
            float sa = 0.f, sb = 0.f;
#pragma unroll
            for (int nt = 0; nt < 8; nt++) {
                int n0 = nt * 8 + quad * 2;
                float2 ua = *(const float2*)(Ua + n0);
                float2 ub = *(const float2*)(Ub + n0);
                float w0 = sm.w2[n0], w1 = sm.w2[n0 + 1];
                sa = fmaf(w0, fmaxf(c[mt][nt][0] + ua.x, 0.f), sa);
                sa = fmaf(w1, fmaxf(c[mt][nt][1] + ua.y, 0.f), sa);
                sb = fmaf(w0, fmaxf(c[mt][nt][2] + ub.x, 0.f), sb);
                sb = fmaf(w1, fmaxf(c[mt][nt][3] + ub.y, 0.f), sb);
            }
            sa += __shfl_xor_sync(0xFFFFFFFF, sa, 1);
            sa += __shfl_xor_sync(0xFFFFFFFF, sa, 2);
            sb += __shfl_xor_sync(0xFFFFFFFF, sb, 1);
            sb += __shfl_xor_sync(0xFFFFFFFF, sb, 2);
            float eva = __expf(sa + sm.b2v);
            float evb = __expf(sb + sm.b2v);
            int ra = rowbase + mt * 16 + g8, rb = ra + 8;
            ej[2 * mt]     = (ra < n) ? eva : 0.f;
            ej[2 * mt + 1] = (rb < n) ? evb : 0.f;
            if (quad == 0) {
                if (ra < n) attn[ra] = eva;     // unnormalized; k_final divides
                if (rb < n) attn[rb] = evb;
            }
        }

        // --- prefetch next tile's x rows into L1 (overlap with phase 2) ----
        {
            int t2 = t + gridDim.x;
            if (t2 < ntiles) {
                int rowbase2 = t2 * 128 + wid * 32;
#pragma unroll
                for (int pf = 0; pf < 4; pf++) {
                    int row = min(rowbase2 + pf * 8 + (lane >> 2), n - 1);
                    const float* p = x + (size_t)row * NF + (lane & 3) * 32;
                    asm volatile("prefetch.global.L1 [%0];" :: "l"(p));
                }
            }
        }

        // --- phase 2 (warp-local): pool this warp's 32 rows ----------------
        {
            float4 acc = make_float4(0.f, 0.f, 0.f, 0.f);
            float acce = 0.f;
            int curg = __shfl_sync(0xFFFFFFFF, gj[0], 0);
#pragma unroll
            for (int r = 0; r < 32; r++) {
                int j   = r >> 3;
                int src = (r & 7) * 4;
                float e = __shfl_sync(0xFFFFFFFF, ej[j], src);
                int   g = __shfl_sync(0xFFFFFFFF, gj[j], src);
                if (g != curg) {
                    red_add_v4(pooled + (size_t)curg * NF + lane * 4, acc);
                    if (lane == 0) atomicAdd(&g_E[curg], acce);
                    acc = make_float4(0.f, 0.f, 0.f, 0.f);
                    acce = 0.f;
                    curg = g;
                }
                int rr = min(rowbase + r, n - 1);
                float4 xv = __ldg((const float4*)(x + (size_t)rr * NF) + lane);
                acc.x = fmaf(xv.x, e, acc.x);
                acc.y = fmaf(xv.y, e, acc.y);
                acc.z = fmaf(xv.z, e, acc.z);
                acc.w = fmaf(xv.w, e, acc.w);
                acce += e;
            }
            red_add_v4(pooled + (size_t)curg * NF + lane * 4, acc);
            if (lane == 0) atomicAdd(&g_E[curg], acce);
        }
    }
}

// ---------------------------------------------------------------------------
// k_final (vectorized): pooled[i] /= E ; attn[j] /= E[batch[j]]
// ---------------------------------------------------------------------------
__global__ void k_final(const int* __restrict__ batch, float* __restrict__ attn,
                        float* __restrict__ pooled, int n) {
    const int pq = NGRAPHS * NF / 4;          // pooled float4 count
    int i = blockIdx.x * 256 + threadIdx.x;
    if (i < pq) {
        float E = g_E[i >> 5];                // 32 float4 per graph row
        float inv = (E > 0.f) ? __fdividef(1.f, E) : 0.f;
        float4 v = ((float4*)pooled)[i];
        v.x *= inv; v.y *= inv; v.z *= inv; v.w *= inv;
        ((float4*)pooled)[i] = v;
    } else {
        int j4 = (i - pq) * 4;
        if (j4 + 3 < n) {
            float4 a = *(const float4*)(attn + j4);
            int4   b = *(const int4*)(batch + j4);
            a.x *= __fdividef(1.f, g_E[b.x]);
            a.y *= __fdividef(1.f, g_E[b.y]);
            a.z *= __fdividef(1.f, g_E[b.z]);
            a.w *= __fdividef(1.f, g_E[b.w]);
            *(float4*)(attn + j4) = a;
        } else {
            for (int j = j4; j < n; j++)
                attn[j] *= __fdividef(1.f, g_E[__ldg(batch + j)]);
        }
    }
}

// ---------------------------------------------------------------------------
extern "C" void kernel_launch(void* const* d_in, const int* in_sizes, int n_in,
                              void* d_out, int out_size) {
    const float* x     = (const float*)d_in[0];
    const float* u     = (const float*)d_in[1];
    const int*   batch = (const int*)  d_in[2];
    const float* W1    = (const float*)d_in[3];
    const float* b1    = (const float*)d_in[4];
    const float* W2    = (const float*)d_in[5];
    const float* b2    = (const float*)d_in[6];

    float* pooled = (float*)d_out;                     // [16384, 128]
    float* attn   = (float*)d_out + NGRAPHS * NF;      // [1e6]

    int n = in_sizes[2];
    int ntiles = (n + 127) / 128;
    int nfinal = NGRAPHS * NF / 4 + (n + 3) / 4;

    k_init<<<256, 256>>>(u, W1, b1, pooled);
    k_mlp_fused<<<592, 128>>>(x, W1, W2, b2, batch, pooled, attn, n, ntiles);
    k_final<<<(nfinal + 255) / 256, 256>>>(batch, attn, pooled, n);
}